// round 3
// baseline (speedup 1.0000x reference)
#include <cuda_runtime.h>

#define BB 8
#define SS 2048
#define EE 1024
#define HH 128

// Scratch for Q/K/V projections (8 MB each) — __device__ globals per harness rules.
__device__ float g_q[BB * SS * HH];
__device__ float g_k[BB * SS * HH];
__device__ float g_v[BB * SS * HH];

// ---------------------------------------------------------------------------
// Kernel 1: QKV projection.  C[16384,128] = X[16384,1024] @ W[1024,128]
// blockIdx.x: 64-row tile of X; blockIdx.y in {0,1,2} selects (wq,wk,wv).
// 256 threads; each computes a 4x8 micro-tile.
// ---------------------------------------------------------------------------
__global__ __launch_bounds__(256) void proj_kernel(
    const float* __restrict__ x, const float* __restrict__ wq,
    const float* __restrict__ wk, const float* __restrict__ wv)
{
    __shared__ float Xs[64][32];
    __shared__ float Ws[32][128];

    const int which = blockIdx.y;
    const float* __restrict__ w = (which == 0) ? wq : (which == 1) ? wk : wv;
    float* __restrict__ out = (which == 0) ? g_q : (which == 1) ? g_k : g_v;

    const int row0 = blockIdx.x * 64;
    const int tid = threadIdx.x;
    const int tx = tid & 15;   // 16 column groups of 8
    const int ty = tid >> 4;   // 16 row groups of 4

    float acc[4][8];
#pragma unroll
    for (int i = 0; i < 4; i++)
#pragma unroll
        for (int j = 0; j < 8; j++) acc[i][j] = 0.0f;

    for (int k0 = 0; k0 < EE; k0 += 32) {
        // Load X tile: 64x32 floats, 2 float4 per thread.
#pragma unroll
        for (int i = 0; i < 2; i++) {
            int idx = (tid + i * 256) * 4;
            int r = idx >> 5, c = idx & 31;
            *(float4*)&Xs[r][c] =
                *(const float4*)&x[(size_t)(row0 + r) * EE + k0 + c];
        }
        // Load W tile: 32x128 floats, 4 float4 per thread.
#pragma unroll
        for (int i = 0; i < 4; i++) {
            int idx = (tid + i * 256) * 4;
            int r = idx >> 7, c = idx & 127;
            *(float4*)&Ws[r][c] =
                *(const float4*)&w[(size_t)(k0 + r) * HH + c];
        }
        __syncthreads();

#pragma unroll
        for (int kk = 0; kk < 32; kk++) {
            float xv[4];
#pragma unroll
            for (int i = 0; i < 4; i++) xv[i] = Xs[ty * 4 + i][kk];
            float4 wa = *(const float4*)&Ws[kk][tx * 8];
            float4 wb = *(const float4*)&Ws[kk][tx * 8 + 4];
            float wv8[8] = {wa.x, wa.y, wa.z, wa.w, wb.x, wb.y, wb.z, wb.w};
#pragma unroll
            for (int i = 0; i < 4; i++)
#pragma unroll
                for (int j = 0; j < 8; j++) acc[i][j] += xv[i] * wv8[j];
        }
        __syncthreads();
    }

#pragma unroll
    for (int i = 0; i < 4; i++) {
        size_t o = (size_t)(row0 + ty * 4 + i) * HH + tx * 8;
        *(float4*)&out[o]     = make_float4(acc[i][0], acc[i][1], acc[i][2], acc[i][3]);
        *(float4*)&out[o + 4] = make_float4(acc[i][4], acc[i][5], acc[i][6], acc[i][7]);
    }
}

// ---------------------------------------------------------------------------
// Kernel 2: flash attention with dropout folded into the numerator.
// Block = (batch b, 64-row Q tile). 256 threads.
// QK phase: thread (ty,tx) owns rows ty*4..+3, cols tx*4..+3 of the 64x64 S tile.
// PV phase: same rows, head cols tx*8..+7. Row ownership identical -> m/l/alpha
// stay in registers, no cross-thread handoff.
// Dynamic smem: Qs/Ks/Vs padded [64][132], Ps [64][68].
// ---------------------------------------------------------------------------
#define QKV_PITCH 132
#define P_PITCH 68
#define ATTN_SMEM_FLOATS (3 * 64 * QKV_PITCH + 64 * P_PITCH)
#define ATTN_SMEM_BYTES (ATTN_SMEM_FLOATS * 4)

__global__ __launch_bounds__(256) void attn_kernel(
    const float* __restrict__ drop_u, float* __restrict__ out)
{
    extern __shared__ float smem[];
    float* Qs = smem;                      // [64][132]
    float* Ks = Qs + 64 * QKV_PITCH;       // [64][132]
    float* Vs = Ks + 64 * QKV_PITCH;       // [64][132]
    float* Ps = Vs + 64 * QKV_PITCH;       // [64][68]

    const int b = blockIdx.y;
    const int q0 = blockIdx.x * 64;
    const int tid = threadIdx.x;
    const int tx = tid & 15;
    const int ty = tid >> 4;

    const float* __restrict__ qg = g_q + (size_t)b * SS * HH;
    const float* __restrict__ kg = g_k + (size_t)b * SS * HH;
    const float* __restrict__ vg = g_v + (size_t)b * SS * HH;
    const float* __restrict__ du = drop_u + (size_t)b * SS * SS;

    // Load Q tile once: 64x128 floats, 8 float4 per thread.
#pragma unroll
    for (int i = 0; i < 8; i++) {
        int idx = (tid + i * 256) * 4;
        int r = idx >> 7, c = idx & 127;
        *(float4*)&Qs[r * QKV_PITCH + c] =
            *(const float4*)&qg[(size_t)(q0 + r) * HH + c];
    }

    float m[4], l[4], o[4][8];
#pragma unroll
    for (int i = 0; i < 4; i++) {
        m[i] = -1e30f;
        l[i] = 0.0f;
#pragma unroll
        for (int j = 0; j < 8; j++) o[i][j] = 0.0f;
    }

    const float scale = 0.03125f;          // 1024^-0.5
    const float inv_keep = 1.0f / 0.9f;

    for (int k0 = 0; k0 < SS; k0 += 64) {
        __syncthreads();   // previous PV reads of Ks/Vs done
        // Load K and V tiles.
#pragma unroll
        for (int i = 0; i < 8; i++) {
            int idx = (tid + i * 256) * 4;
            int r = idx >> 7, c = idx & 127;
            *(float4*)&Ks[r * QKV_PITCH + c] =
                *(const float4*)&kg[(size_t)(k0 + r) * HH + c];
            *(float4*)&Vs[r * QKV_PITCH + c] =
                *(const float4*)&vg[(size_t)(k0 + r) * HH + c];
        }
        // Prefetch dropout tile entries owned by this thread (overlaps with QK).
        float4 dr[4];
#pragma unroll
        for (int i = 0; i < 4; i++)
            dr[i] = *(const float4*)&du[(size_t)(q0 + ty * 4 + i) * SS + k0 + tx * 4];
        __syncthreads();

        // ---- S = scale * Q K^T  (4x4 per thread) ----
        float s[4][4];
#pragma unroll
        for (int i = 0; i < 4; i++)
#pragma unroll
            for (int j = 0; j < 4; j++) s[i][j] = 0.0f;

#pragma unroll
        for (int h = 0; h < HH; h += 4) {
            float4 qv[4], kv[4];
#pragma unroll
            for (int i = 0; i < 4; i++)
                qv[i] = *(const float4*)&Qs[(ty * 4 + i) * QKV_PITCH + h];
#pragma unroll
            for (int j = 0; j < 4; j++)
                kv[j] = *(const float4*)&Ks[(tx * 4 + j) * QKV_PITCH + h];
#pragma unroll
            for (int i = 0; i < 4; i++)
#pragma unroll
                for (int j = 0; j < 4; j++) {
                    s[i][j] += qv[i].x * kv[j].x;
                    s[i][j] += qv[i].y * kv[j].y;
                    s[i][j] += qv[i].z * kv[j].z;
                    s[i][j] += qv[i].w * kv[j].w;
                }
        }

        // ---- online softmax (+ dropout into numerator only) ----
        float alpha[4];
#pragma unroll
        for (int i = 0; i < 4; i++) {
            float p0 = s[i][0] * scale, p1 = s[i][1] * scale;
            float p2 = s[i][2] * scale, p3 = s[i][3] * scale;
            float mt = fmaxf(fmaxf(p0, p1), fmaxf(p2, p3));
#pragma unroll
            for (int off = 8; off > 0; off >>= 1)
                mt = fmaxf(mt, __shfl_xor_sync(0xffffffffu, mt, off));
            float mn = fmaxf(m[i], mt);
            p0 = __expf(p0 - mn); p1 = __expf(p1 - mn);
            p2 = __expf(p2 - mn); p3 = __expf(p3 - mn);
            float sum = p0 + p1 + p2 + p3;
#pragma unroll
            for (int off = 8; off > 0; off >>= 1)
                sum += __shfl_xor_sync(0xffffffffu, sum, off);
            alpha[i] = __expf(m[i] - mn);
            l[i] = l[i] * alpha[i] + sum;   // denominator WITHOUT dropout
            m[i] = mn;
            // dropout applied only to numerator P
            p0 *= (dr[i].x >= 0.1f) ? inv_keep : 0.0f;
            p1 *= (dr[i].y >= 0.1f) ? inv_keep : 0.0f;
            p2 *= (dr[i].z >= 0.1f) ? inv_keep : 0.0f;
            p3 *= (dr[i].w >= 0.1f) ? inv_keep : 0.0f;
            *(float4*)&Ps[(ty * 4 + i) * P_PITCH + tx * 4] =
                make_float4(p0, p1, p2, p3);
        }
        __syncthreads();

        // ---- O = O*alpha + P V  (4 rows x 8 head cols per thread) ----
#pragma unroll
        for (int i = 0; i < 4; i++)
#pragma unroll
            for (int j = 0; j < 8; j++) o[i][j] *= alpha[i];

#pragma unroll 4
        for (int c = 0; c < 64; c++) {
            float pv[4];
#pragma unroll
            for (int i = 0; i < 4; i++) pv[i] = Ps[(ty * 4 + i) * P_PITCH + c];
            float4 va = *(const float4*)&Vs[c * QKV_PITCH + tx * 8];
            float4 vb = *(const float4*)&Vs[c * QKV_PITCH + tx * 8 + 4];
#pragma unroll
            for (int i = 0; i < 4; i++) {
                o[i][0] += pv[i] * va.x;
                o[i][1] += pv[i] * va.y;
                o[i][2] += pv[i] * va.z;
                o[i][3] += pv[i] * va.w;
                o[i][4] += pv[i] * vb.x;
                o[i][5] += pv[i] * vb.y;
                o[i][6] += pv[i] * vb.z;
                o[i][7] += pv[i] * vb.w;
            }
        }
    }

    // epilogue: divide by softmax denominator, store
#pragma unroll
    for (int i = 0; i < 4; i++) {
        float inv = 1.0f / l[i];
        size_t oidx = (size_t)b * SS * HH + (size_t)(q0 + ty * 4 + i) * HH + tx * 8;
        *(float4*)&out[oidx] =
            make_float4(o[i][0] * inv, o[i][1] * inv, o[i][2] * inv, o[i][3] * inv);
        *(float4*)&out[oidx + 4] =
            make_float4(o[i][4] * inv, o[i][5] * inv, o[i][6] * inv, o[i][7] * inv);
    }
}

extern "C" void kernel_launch(void* const* d_in, const int* in_sizes, int n_in,
                              void* d_out, int out_size)
{
    const float* x  = (const float*)d_in[0];
    const float* wq = (const float*)d_in[1];
    const float* wk = (const float*)d_in[2];
    const float* wv = (const float*)d_in[3];
    const float* du = (const float*)d_in[4];
    float* out = (float*)d_out;

    cudaFuncSetAttribute(attn_kernel,
                         cudaFuncAttributeMaxDynamicSharedMemorySize,
                         ATTN_SMEM_BYTES);

    dim3 g1(BB * SS / 64, 3);
    proj_kernel<<<g1, 256>>>(x, wq, wk, wv);

    dim3 g2(SS / 64, BB);
    attn_kernel<<<g2, 256, ATTN_SMEM_BYTES>>>(du, out);
}